// round 1
// baseline (speedup 1.0000x reference)
#include <cuda_runtime.h>
#include <math.h>

#define B_  4
#define T_  2048
#define H_  1024
#define NH_ 16
#define HD_ 64
#define M_  (B_ * T_)   // 8192
#define KD_ H_          // 1024 (GEMM reduction dim)
#define N_  H_          // 1024

// Scratch for projected Q, K, V (no cudaMalloc allowed).
__device__ float g_Q[M_ * H_];
__device__ float g_K[M_ * H_];
__device__ float g_V[M_ * H_];

// ---------------------------------------------------------------------------
// QKV projection: out[m, n] = sum_k X[m, k] * W[n, k] + b[n]
// (torch Linear: x @ W.T + b; both X and W are K-major -> NT GEMM)
// 128x128 tile, BK=16, 8x8 per-thread register block, 256 threads.
// ---------------------------------------------------------------------------
#define GBM 128
#define GBN 128
#define GBK 16

__global__ __launch_bounds__(256) void qkv_gemm(
    const float* __restrict__ X,
    const float* __restrict__ W,
    const float* __restrict__ bias,
    float* __restrict__ out)
{
    __shared__ float As[GBK][GBM];
    __shared__ float Bs[GBK][GBN];

    const int tid = threadIdx.x;
    const int bm = blockIdx.y * GBM;
    const int bn = blockIdx.x * GBN;
    const int tx = tid & 15;   // 0..15  -> n block of 8
    const int ty = tid >> 4;   // 0..15  -> m block of 8

    float acc[8][8];
    #pragma unroll
    for (int i = 0; i < 8; i++)
        #pragma unroll
        for (int j = 0; j < 8; j++) acc[i][j] = 0.f;

    for (int k0 = 0; k0 < KD_; k0 += GBK) {
        // Load A tile: X[bm..bm+127][k0..k0+15], 512 float4, 2 per thread.
        #pragma unroll
        for (int i = 0; i < 2; i++) {
            int idx = tid + 256 * i;          // float4 index 0..511
            int row = idx >> 2;               // 0..127
            int c4  = idx & 3;                // 0..3
            float4 v = *(const float4*)(X + (size_t)(bm + row) * KD_ + k0 + c4 * 4);
            As[c4 * 4 + 0][row] = v.x;
            As[c4 * 4 + 1][row] = v.y;
            As[c4 * 4 + 2][row] = v.z;
            As[c4 * 4 + 3][row] = v.w;
        }
        // Load B tile: W[bn..bn+127][k0..k0+15]
        #pragma unroll
        for (int i = 0; i < 2; i++) {
            int idx = tid + 256 * i;
            int row = idx >> 2;
            int c4  = idx & 3;
            float4 v = *(const float4*)(W + (size_t)(bn + row) * KD_ + k0 + c4 * 4);
            Bs[c4 * 4 + 0][row] = v.x;
            Bs[c4 * 4 + 1][row] = v.y;
            Bs[c4 * 4 + 2][row] = v.z;
            Bs[c4 * 4 + 3][row] = v.w;
        }
        __syncthreads();

        #pragma unroll
        for (int kk = 0; kk < GBK; kk++) {
            float a[8], b[8];
            float4 a0 = *(float4*)&As[kk][ty * 8];
            float4 a1 = *(float4*)&As[kk][ty * 8 + 4];
            a[0]=a0.x; a[1]=a0.y; a[2]=a0.z; a[3]=a0.w;
            a[4]=a1.x; a[5]=a1.y; a[6]=a1.z; a[7]=a1.w;
            float4 b0 = *(float4*)&Bs[kk][tx * 8];
            float4 b1 = *(float4*)&Bs[kk][tx * 8 + 4];
            b[0]=b0.x; b[1]=b0.y; b[2]=b0.z; b[3]=b0.w;
            b[4]=b1.x; b[5]=b1.y; b[6]=b1.z; b[7]=b1.w;
            #pragma unroll
            for (int i = 0; i < 8; i++)
                #pragma unroll
                for (int j = 0; j < 8; j++)
                    acc[i][j] += a[i] * b[j];
        }
        __syncthreads();
    }

    // Write out + bias (float4 stores)
    #pragma unroll
    for (int i = 0; i < 8; i++) {
        int m = bm + ty * 8 + i;
        float* op = out + (size_t)m * N_ + bn + tx * 8;
        const float* bp = bias + bn + tx * 8;
        #pragma unroll
        for (int j4 = 0; j4 < 2; j4++) {
            float4 r;
            r.x = acc[i][j4*4+0] + bp[j4*4+0];
            r.y = acc[i][j4*4+1] + bp[j4*4+1];
            r.z = acc[i][j4*4+2] + bp[j4*4+2];
            r.w = acc[i][j4*4+3] + bp[j4*4+3];
            *(float4*)(op + j4 * 4) = r;
        }
    }
}

// ---------------------------------------------------------------------------
// Causal flash attention, fp32.
// Grid: (T/64, NH, B). Block: 64 threads, one thread per query row.
// K/V tiles of 64 rows staged in shared (all threads read same address ->
// broadcast, conflict-free). Online softmax in chunks of 16 scores.
// ---------------------------------------------------------------------------
#define ABM 64
#define ABN 64

__global__ __launch_bounds__(64) void attn_kernel(
    const float* __restrict__ mask,   // [B, 1, 1, T] additive
    float* __restrict__ out)
{
    __shared__ float Ks[ABN][HD_];
    __shared__ float Vs[ABN][HD_];
    __shared__ float Ms[ABN];

    const int r  = threadIdx.x;           // query row within block (0..63)
    const int qb = blockIdx.x;            // query tile
    const int h  = blockIdx.y;            // head
    const int b  = blockIdx.z;            // batch
    const int qi = qb * ABM + r;          // global query index
    const float scale = 0.125f;           // 64^-0.5

    // Load q row into registers (64 floats)
    float q[HD_];
    const float* qp = g_Q + (size_t)(b * T_ + qi) * H_ + h * HD_;
    #pragma unroll
    for (int d4 = 0; d4 < 16; d4++) {
        float4 v = *(const float4*)(qp + d4 * 4);
        q[d4*4+0] = v.x; q[d4*4+1] = v.y; q[d4*4+2] = v.z; q[d4*4+3] = v.w;
    }

    float m = -1e30f, l = 0.f;
    float acc[HD_];
    #pragma unroll
    for (int d = 0; d < HD_; d++) acc[d] = 0.f;

    for (int kb = 0; kb <= qb; kb++) {
        // Cooperative load of K/V tile: 64x64 floats = 1024 float4 each.
        const float* kp = g_K + (size_t)(b * T_ + kb * ABN) * H_ + h * HD_;
        const float* vp = g_V + (size_t)(b * T_ + kb * ABN) * H_ + h * HD_;
        #pragma unroll
        for (int i = 0; i < 16; i++) {
            int idx = r + 64 * i;          // float4 index 0..1023
            int j   = idx >> 4;            // row 0..63
            int d4  = idx & 15;            // float4 within row
            *(float4*)&Ks[j][d4 * 4] = *(const float4*)(kp + (size_t)j * H_ + d4 * 4);
            *(float4*)&Vs[j][d4 * 4] = *(const float4*)(vp + (size_t)j * H_ + d4 * 4);
        }
        Ms[r] = mask[(size_t)b * T_ + kb * ABN + r];
        __syncthreads();

        // Process the 64 keys in chunks of 16 (register-friendly).
        #pragma unroll 1
        for (int j0 = 0; j0 < ABN; j0 += 16) {
            float s[16];
            float cm = -1e30f;
            #pragma unroll
            for (int jj = 0; jj < 16; jj++) {
                int j = j0 + jj;
                float dot = 0.f;
                #pragma unroll
                for (int d4 = 0; d4 < 16; d4++) {
                    float4 kv = *(float4*)&Ks[j][d4 * 4];
                    dot += q[d4*4+0] * kv.x;
                    dot += q[d4*4+1] * kv.y;
                    dot += q[d4*4+2] * kv.z;
                    dot += q[d4*4+3] * kv.w;
                }
                float sv = dot * scale + Ms[j];
                if (kb * ABN + j > qi) sv = -1e30f;   // causal
                s[jj] = sv;
                cm = fmaxf(cm, sv);
            }
            float mn = fmaxf(m, cm);
            float corr = __expf(m - mn);
            l *= corr;
            #pragma unroll
            for (int d = 0; d < HD_; d++) acc[d] *= corr;
            m = mn;
            #pragma unroll
            for (int jj = 0; jj < 16; jj++) {
                int j = j0 + jj;
                float p = __expf(s[jj] - m);
                l += p;
                #pragma unroll
                for (int d4 = 0; d4 < 16; d4++) {
                    float4 vv = *(float4*)&Vs[j][d4 * 4];
                    acc[d4*4+0] += p * vv.x;
                    acc[d4*4+1] += p * vv.y;
                    acc[d4*4+2] += p * vv.z;
                    acc[d4*4+3] += p * vv.w;
                }
            }
        }
        __syncthreads();
    }

    const float inv = 1.f / l;
    float* op = out + (size_t)(b * T_ + qi) * H_ + h * HD_;
    #pragma unroll
    for (int d4 = 0; d4 < 16; d4++) {
        float4 o;
        o.x = acc[d4*4+0] * inv;
        o.y = acc[d4*4+1] * inv;
        o.z = acc[d4*4+2] * inv;
        o.w = acc[d4*4+3] * inv;
        *(float4*)(op + d4 * 4) = o;
    }
}

// ---------------------------------------------------------------------------
// Launch
// ---------------------------------------------------------------------------
extern "C" void kernel_launch(void* const* d_in, const int* in_sizes, int n_in,
                              void* d_out, int out_size)
{
    const float* x    = (const float*)d_in[0];  // hidden_states [B,T,H]
    const float* mask = (const float*)d_in[1];  // attention_mask [B,1,1,T]
    const float* Wq   = (const float*)d_in[2];
    const float* bq   = (const float*)d_in[3];
    const float* Wk   = (const float*)d_in[4];
    const float* bk   = (const float*)d_in[5];
    const float* Wv   = (const float*)d_in[6];
    const float* bv   = (const float*)d_in[7];
    float* out = (float*)d_out;

    float *Qp, *Kp, *Vp;
    cudaGetSymbolAddress((void**)&Qp, g_Q);
    cudaGetSymbolAddress((void**)&Kp, g_K);
    cudaGetSymbolAddress((void**)&Vp, g_V);

    dim3 ggrid(N_ / GBN, M_ / GBM);   // (8, 64)
    qkv_gemm<<<ggrid, 256>>>(x, Wq, bq, Qp);
    qkv_gemm<<<ggrid, 256>>>(x, Wk, bk, Kp);
    qkv_gemm<<<ggrid, 256>>>(x, Wv, bv, Vp);

    dim3 agrid(T_ / ABM, NH_, B_);    // (32, 16, 4)
    attn_kernel<<<agrid, 64>>>(mask, out);
}

// round 2
// speedup vs baseline: 3.1047x; 3.1047x over previous
#include <cuda_runtime.h>
#include <math.h>
#include <stdint.h>

#define B_  4
#define T_  2048
#define H_  1024
#define NH_ 16
#define HD_ 64
#define M_  (B_ * T_)   // 8192

// Scratch for projected Q, K, V (no cudaMalloc allowed).
__device__ float g_Q[M_ * H_];
__device__ float g_K[M_ * H_];
__device__ float g_V[M_ * H_];

// ---------------------------------------------------------------------------
// Helpers: tf32 conversion + m16n8k8 tf32 mma
// ---------------------------------------------------------------------------
__device__ __forceinline__ uint32_t f2tf(float x) {
    uint32_t r;
    asm("cvt.rna.tf32.f32 %0, %1;" : "=r"(r) : "f"(x));
    return r;
}

__device__ __forceinline__ void mma_tf32(float d[4], const uint32_t a[4], const uint32_t b[2]) {
    asm volatile(
        "mma.sync.aligned.m16n8k8.row.col.f32.tf32.tf32.f32 "
        "{%0,%1,%2,%3}, {%4,%5,%6,%7}, {%8,%9}, {%0,%1,%2,%3};\n"
        : "+f"(d[0]), "+f"(d[1]), "+f"(d[2]), "+f"(d[3])
        : "r"(a[0]), "r"(a[1]), "r"(a[2]), "r"(a[3]),
          "r"(b[0]), "r"(b[1]));
}

// Fragment mapping (PTX m16n8k8 tf32), lane = 32 threads, g = lane>>2, c = lane&3:
//   A (16x8 row-major):  a0=(g, c)  a1=(g+8, c)  a2=(g, c+4)  a3=(g+8, c+4)
//   B (8x8,  B[k][n]):   b0=(c, g)  b1=(c+4, g)
//   C (16x8):            c0=(g, 2c) c1=(g, 2c+1) c2=(g+8, 2c) c3=(g+8, 2c+1)

// ---------------------------------------------------------------------------
// QKV projection: out[m,n] = sum_k X[m,k] * W[n,k] + b[n]   (NT GEMM)
// 128x128x32 tiles, 8 warps (4x2), warp tile 32x64.
// Shared stride 36: frag-load bank = (4*row + k) % 32 -> conflict-free.
// ---------------------------------------------------------------------------
#define GBM 128
#define GBN 128
#define GBK 32
#define LDA 36

__global__ __launch_bounds__(256) void qkv_gemm_tc(
    const float* __restrict__ X,
    const float* __restrict__ W,
    const float* __restrict__ bias,
    float* __restrict__ out)
{
    __shared__ uint32_t As[GBM * LDA];
    __shared__ uint32_t Bs[GBN * LDA];

    const int tid  = threadIdx.x;
    const int lane = tid & 31;
    const int wid  = tid >> 5;
    const int bm   = blockIdx.y * GBM;
    const int bn   = blockIdx.x * GBN;
    const int moff = (wid & 3) * 32;
    const int noff = (wid >> 2) * 64;
    const int g    = lane >> 2;
    const int c    = lane & 3;

    float d[2][8][4];
    #pragma unroll
    for (int mt = 0; mt < 2; mt++)
        #pragma unroll
        for (int nt = 0; nt < 8; nt++)
            #pragma unroll
            for (int e = 0; e < 4; e++) d[mt][nt][e] = 0.f;

    for (int k0 = 0; k0 < H_; k0 += GBK) {
        // Stage X and W tiles (128 rows x 8 float4 each), cvt to tf32.
        #pragma unroll
        for (int i = 0; i < 4; i++) {
            int idx = tid + 256 * i;
            int row = idx >> 3;
            int c4  = idx & 7;
            float4 v = *(const float4*)(X + (size_t)(bm + row) * H_ + k0 + c4 * 4);
            uint4 u;
            u.x = f2tf(v.x); u.y = f2tf(v.y); u.z = f2tf(v.z); u.w = f2tf(v.w);
            *(uint4*)&As[row * LDA + c4 * 4] = u;
            float4 w = *(const float4*)(W + (size_t)(bn + row) * H_ + k0 + c4 * 4);
            uint4 uw;
            uw.x = f2tf(w.x); uw.y = f2tf(w.y); uw.z = f2tf(w.z); uw.w = f2tf(w.w);
            *(uint4*)&Bs[row * LDA + c4 * 4] = uw;
        }
        __syncthreads();

        #pragma unroll
        for (int ks = 0; ks < GBK / 8; ks++) {
            const int kk = ks * 8;
            uint32_t a[2][4];
            #pragma unroll
            for (int mt = 0; mt < 2; mt++) {
                int r0 = moff + mt * 16 + g;
                a[mt][0] = As[r0 * LDA + kk + c];
                a[mt][1] = As[(r0 + 8) * LDA + kk + c];
                a[mt][2] = As[r0 * LDA + kk + c + 4];
                a[mt][3] = As[(r0 + 8) * LDA + kk + c + 4];
            }
            uint32_t bf[8][2];
            #pragma unroll
            for (int nt = 0; nt < 8; nt++) {
                int n0 = noff + nt * 8 + g;
                bf[nt][0] = Bs[n0 * LDA + kk + c];
                bf[nt][1] = Bs[n0 * LDA + kk + c + 4];
            }
            #pragma unroll
            for (int mt = 0; mt < 2; mt++)
                #pragma unroll
                for (int nt = 0; nt < 8; nt++)
                    mma_tf32(d[mt][nt], a[mt], bf[nt]);
        }
        __syncthreads();
    }

    // Epilogue: add bias, float2 stores.
    #pragma unroll
    for (int mt = 0; mt < 2; mt++) {
        int row = bm + moff + mt * 16 + g;
        #pragma unroll
        for (int nt = 0; nt < 8; nt++) {
            int col = bn + noff + nt * 8 + 2 * c;
            float2 bv = *(const float2*)(bias + col);
            float2 r0, r1;
            r0.x = d[mt][nt][0] + bv.x; r0.y = d[mt][nt][1] + bv.y;
            r1.x = d[mt][nt][2] + bv.x; r1.y = d[mt][nt][3] + bv.y;
            *(float2*)(out + (size_t)row * H_ + col)       = r0;
            *(float2*)(out + (size_t)(row + 8) * H_ + col) = r1;
        }
    }
}

// ---------------------------------------------------------------------------
// Flash attention with tf32 mma. Block = 128 threads (4 warps), tile 64x64.
// Warp w owns query rows [w*16, w*16+16). S and PV via m16n8k8.
// P is staged through the K-tile buffer (K is dead after S).
// Shared strides: Qs/Ks/Ps = 68 ((4g+c)%32 pattern), Vs = 72 ((8c+g)%32).
// ---------------------------------------------------------------------------
#define LQ 68
#define LV 72
// words: Qs 64*68 + Ks 64*68 + Vs 64*72 + Ms 64 = 13376 -> 53504 bytes
#define ATT_SMEM_BYTES ((64 * LQ * 2 + 64 * LV + 64) * 4)

__global__ __launch_bounds__(128) void attn_tc(
    const float* __restrict__ mask,
    float* __restrict__ out)
{
    extern __shared__ uint32_t sm[];
    uint32_t* Qs = sm;
    uint32_t* Ks = sm + 64 * LQ;          // also reused as P after S-phase
    uint32_t* Vs = Ks + 64 * LQ;
    float*    Ms = (float*)(Vs + 64 * LV);

    const int tid  = threadIdx.x;
    const int lane = tid & 31;
    const int wid  = tid >> 5;
    const int qb   = blockIdx.x;
    const int h    = blockIdx.y;
    const int b    = blockIdx.z;
    const int g    = lane >> 2;
    const int c    = lane & 3;
    const int r0l  = wid * 16 + g;        // local frag row (set 0)
    const int qrow0 = qb * 64 + r0l;      // global query row (set 0); set 1 = +8

    // Load Q tile once: scale by 1/8 (exact) then cvt to tf32.
    const float* qg = g_Q + ((size_t)(b * T_) + (size_t)qb * 64) * H_ + h * HD_;
    #pragma unroll
    for (int i = 0; i < 8; i++) {
        int idx = tid + 128 * i;
        int row = idx >> 4, c4 = idx & 15;
        float4 v = *(const float4*)(qg + (size_t)row * H_ + c4 * 4);
        uint4 u;
        u.x = f2tf(v.x * 0.125f); u.y = f2tf(v.y * 0.125f);
        u.z = f2tf(v.z * 0.125f); u.w = f2tf(v.w * 0.125f);
        *(uint4*)&Qs[row * LQ + c4 * 4] = u;
    }

    float o[8][4];
    #pragma unroll
    for (int nt = 0; nt < 8; nt++)
        #pragma unroll
        for (int e = 0; e < 4; e++) o[nt][e] = 0.f;
    float m0 = -1e30f, m1 = -1e30f, l0 = 0.f, l1 = 0.f;

    for (int kb = 0; kb <= qb; kb++) {
        __syncthreads();   // previous iteration's readers of Ks(P)/Vs are done
        const float* kg = g_K + ((size_t)(b * T_) + (size_t)kb * 64) * H_ + h * HD_;
        const float* vg = g_V + ((size_t)(b * T_) + (size_t)kb * 64) * H_ + h * HD_;
        #pragma unroll
        for (int i = 0; i < 8; i++) {
            int idx = tid + 128 * i;
            int row = idx >> 4, c4 = idx & 15;
            float4 kv = *(const float4*)(kg + (size_t)row * H_ + c4 * 4);
            uint4 uk;
            uk.x = f2tf(kv.x); uk.y = f2tf(kv.y); uk.z = f2tf(kv.z); uk.w = f2tf(kv.w);
            *(uint4*)&Ks[row * LQ + c4 * 4] = uk;
            float4 vv = *(const float4*)(vg + (size_t)row * H_ + c4 * 4);
            uint4 uv;
            uv.x = f2tf(vv.x); uv.y = f2tf(vv.y); uv.z = f2tf(vv.z); uv.w = f2tf(vv.w);
            *(uint4*)&Vs[row * LV + c4 * 4] = uv;
        }
        if (tid < 64) Ms[tid] = mask[(size_t)b * T_ + kb * 64 + tid];
        __syncthreads();

        // ---- S = (Q*scale) K^T ----
        float s[8][4];
        #pragma unroll
        for (int nt = 0; nt < 8; nt++)
            #pragma unroll
            for (int e = 0; e < 4; e++) s[nt][e] = 0.f;

        #pragma unroll
        for (int ks = 0; ks < 8; ks++) {
            const int kk = ks * 8;
            uint32_t a[4];
            a[0] = Qs[r0l * LQ + kk + c];
            a[1] = Qs[(r0l + 8) * LQ + kk + c];
            a[2] = Qs[r0l * LQ + kk + c + 4];
            a[3] = Qs[(r0l + 8) * LQ + kk + c + 4];
            #pragma unroll
            for (int nt = 0; nt < 8; nt++) {
                uint32_t bf[2];
                int n0 = nt * 8 + g;
                bf[0] = Ks[n0 * LQ + kk + c];
                bf[1] = Ks[n0 * LQ + kk + c + 4];
                mma_tf32(s[nt], a, bf);
            }
        }

        // ---- mask + online softmax ----
        float rmax0 = -1e30f, rmax1 = -1e30f;
        #pragma unroll
        for (int nt = 0; nt < 8; nt++) {
            int lc  = nt * 8 + 2 * c;
            int col = kb * 64 + lc;
            float mk0 = Ms[lc], mk1 = Ms[lc + 1];
            s[nt][0] += mk0; s[nt][1] += mk1;
            s[nt][2] += mk0; s[nt][3] += mk1;
            if (col     > qrow0)     s[nt][0] = -1e30f;
            if (col + 1 > qrow0)     s[nt][1] = -1e30f;
            if (col     > qrow0 + 8) s[nt][2] = -1e30f;
            if (col + 1 > qrow0 + 8) s[nt][3] = -1e30f;
            rmax0 = fmaxf(rmax0, fmaxf(s[nt][0], s[nt][1]));
            rmax1 = fmaxf(rmax1, fmaxf(s[nt][2], s[nt][3]));
        }
        rmax0 = fmaxf(rmax0, __shfl_xor_sync(0xffffffffu, rmax0, 1));
        rmax0 = fmaxf(rmax0, __shfl_xor_sync(0xffffffffu, rmax0, 2));
        rmax1 = fmaxf(rmax1, __shfl_xor_sync(0xffffffffu, rmax1, 1));
        rmax1 = fmaxf(rmax1, __shfl_xor_sync(0xffffffffu, rmax1, 2));

        float mn0 = fmaxf(m0, rmax0), mn1 = fmaxf(m1, rmax1);
        float cr0 = __expf(m0 - mn0), cr1 = __expf(m1 - mn1);
        m0 = mn0; m1 = mn1;
        l0 *= cr0; l1 *= cr1;

        float ps0 = 0.f, ps1 = 0.f;
        #pragma unroll
        for (int nt = 0; nt < 8; nt++) {
            s[nt][0] = __expf(s[nt][0] - m0);
            s[nt][1] = __expf(s[nt][1] - m0);
            s[nt][2] = __expf(s[nt][2] - m1);
            s[nt][3] = __expf(s[nt][3] - m1);
            ps0 += s[nt][0] + s[nt][1];
            ps1 += s[nt][2] + s[nt][3];
            o[nt][0] *= cr0; o[nt][1] *= cr0;
            o[nt][2] *= cr1; o[nt][3] *= cr1;
        }
        ps0 += __shfl_xor_sync(0xffffffffu, ps0, 1);
        ps0 += __shfl_xor_sync(0xffffffffu, ps0, 2);
        ps1 += __shfl_xor_sync(0xffffffffu, ps1, 1);
        ps1 += __shfl_xor_sync(0xffffffffu, ps1, 2);
        l0 += ps0; l1 += ps1;

        // All warps must finish reading Ks before it is overwritten with P.
        __syncthreads();

        // ---- stage P (tf32) into Ks buffer; warp-local rows only ----
        #pragma unroll
        for (int nt = 0; nt < 8; nt++) {
            int lc = nt * 8 + 2 * c;
            uint2 p01; p01.x = f2tf(s[nt][0]); p01.y = f2tf(s[nt][1]);
            uint2 p23; p23.x = f2tf(s[nt][2]); p23.y = f2tf(s[nt][3]);
            *(uint2*)&Ks[r0l * LQ + lc]       = p01;
            *(uint2*)&Ks[(r0l + 8) * LQ + lc] = p23;
        }
        __syncwarp();

        // ---- O += P V ----
        #pragma unroll
        for (int ks = 0; ks < 8; ks++) {
            const int kk = ks * 8;
            uint32_t a[4];
            a[0] = Ks[r0l * LQ + kk + c];
            a[1] = Ks[(r0l + 8) * LQ + kk + c];
            a[2] = Ks[r0l * LQ + kk + c + 4];
            a[3] = Ks[(r0l + 8) * LQ + kk + c + 4];
            #pragma unroll
            for (int nt = 0; nt < 8; nt++) {
                uint32_t bf[2];
                bf[0] = Vs[(kk + c) * LV + nt * 8 + g];
                bf[1] = Vs[(kk + c + 4) * LV + nt * 8 + g];
                mma_tf32(o[nt], a, bf);
            }
        }
    }

    // ---- epilogue: normalize and store ----
    float inv0 = 1.f / l0, inv1 = 1.f / l1;
    float* og = out + ((size_t)(b * T_) + (size_t)qb * 64 + r0l) * H_ + h * HD_;
    #pragma unroll
    for (int nt = 0; nt < 8; nt++) {
        int lc = nt * 8 + 2 * c;
        float2 w0, w1;
        w0.x = o[nt][0] * inv0; w0.y = o[nt][1] * inv0;
        w1.x = o[nt][2] * inv1; w1.y = o[nt][3] * inv1;
        *(float2*)(og + lc)          = w0;
        *(float2*)(og + 8 * H_ + lc) = w1;
    }
}

// ---------------------------------------------------------------------------
// Launch
// ---------------------------------------------------------------------------
extern "C" void kernel_launch(void* const* d_in, const int* in_sizes, int n_in,
                              void* d_out, int out_size)
{
    const float* x    = (const float*)d_in[0];
    const float* mask = (const float*)d_in[1];
    const float* Wq   = (const float*)d_in[2];
    const float* bq   = (const float*)d_in[3];
    const float* Wk   = (const float*)d_in[4];
    const float* bk   = (const float*)d_in[5];
    const float* Wv   = (const float*)d_in[6];
    const float* bv   = (const float*)d_in[7];
    float* out = (float*)d_out;

    float *Qp, *Kp, *Vp;
    cudaGetSymbolAddress((void**)&Qp, g_Q);
    cudaGetSymbolAddress((void**)&Kp, g_K);
    cudaGetSymbolAddress((void**)&Vp, g_V);

    cudaFuncSetAttribute(attn_tc, cudaFuncAttributeMaxDynamicSharedMemorySize,
                         ATT_SMEM_BYTES);

    dim3 ggrid(H_ / GBN, M_ / GBM);   // (8, 64)
    qkv_gemm_tc<<<ggrid, 256>>>(x, Wq, bq, Qp);
    qkv_gemm_tc<<<ggrid, 256>>>(x, Wk, bk, Kp);
    qkv_gemm_tc<<<ggrid, 256>>>(x, Wv, bv, Vp);

    dim3 agrid(T_ / 64, NH_, B_);     // (32, 16, 4)
    attn_tc<<<agrid, 128, ATT_SMEM_BYTES>>>(mask, out);
}

// round 5
// speedup vs baseline: 6.3398x; 2.0420x over previous
#include <cuda_runtime.h>
#include <cuda_fp16.h>
#include <math.h>
#include <stdint.h>

#define B_  4
#define T_  2048
#define H_  1024
#define NH_ 16
#define HD_ 64
#define M_  (B_ * T_)   // 8192

// Scratch for projected Q(pre-scaled), K, V in fp16.
__device__ __half g_Q[M_ * H_];
__device__ __half g_K[M_ * H_];
__device__ __half g_V[M_ * H_];

// ---------------------------------------------------------------------------
// mma.m16n8k16 f16 (f32 accum) + ldmatrix helpers
// ---------------------------------------------------------------------------
__device__ __forceinline__ void mma_f16(float d[4], const uint32_t a[4], const uint32_t b[2]) {
    asm volatile(
        "mma.sync.aligned.m16n8k16.row.col.f32.f16.f16.f32 "
        "{%0,%1,%2,%3}, {%4,%5,%6,%7}, {%8,%9}, {%0,%1,%2,%3};\n"
        : "+f"(d[0]), "+f"(d[1]), "+f"(d[2]), "+f"(d[3])
        : "r"(a[0]), "r"(a[1]), "r"(a[2]), "r"(a[3]), "r"(b[0]), "r"(b[1]));
}

__device__ __forceinline__ void ldsm4(uint32_t addr, uint32_t &r0, uint32_t &r1,
                                      uint32_t &r2, uint32_t &r3) {
    asm volatile("ldmatrix.sync.aligned.m8n8.x4.shared.b16 {%0,%1,%2,%3}, [%4];"
                 : "=r"(r0), "=r"(r1), "=r"(r2), "=r"(r3) : "r"(addr));
}

__device__ __forceinline__ void ldsm4t(uint32_t addr, uint32_t &r0, uint32_t &r1,
                                       uint32_t &r2, uint32_t &r3) {
    asm volatile("ldmatrix.sync.aligned.m8n8.x4.trans.shared.b16 {%0,%1,%2,%3}, [%4];"
                 : "=r"(r0), "=r"(r1), "=r"(r2), "=r"(r3) : "r"(addr));
}

// Fragment maps (g = lane>>2, c = lane&3):
//   A: a0=A[g][2c,2c+1] a1=A[g+8][..] a2=A[g][2c+8,..] a3=A[g+8][2c+8,..]
//   B (col-major KxN): b0={B[2c][g],B[2c+1][g]} b1={B[2c+8][g],B[2c+9][g]}
//   C: c0=(g,2c) c1=(g,2c+1) c2=(g+8,2c) c3=(g+8,2c+1)

// ---------------------------------------------------------------------------
// Fused QKV projection: z in {0,1,2} selects (Wq->Q*0.125, Wk->K, Wv->V).
// out[m,n] = (sum_k X[m,k]*W[n,k] + b[n]) * scale, stored fp16.
// 128x128x32 tiles, 8 warps (4m x 2n), warp tile 32x64. LDA=40 halves (80B)
// -> ldmatrix rows rotate 5 chunks mod 8 => conflict-free.
// ---------------------------------------------------------------------------
#define GBM 128
#define GBN 128
#define GBK 32
#define LDA 40

__global__ __launch_bounds__(256) void qkv_gemm_fp16(
    const float* __restrict__ X,
    const float* __restrict__ Wq, const float* __restrict__ bq,
    const float* __restrict__ Wk, const float* __restrict__ bk,
    const float* __restrict__ Wv, const float* __restrict__ bv)
{
    __shared__ __align__(16) __half As[GBM * LDA];
    __shared__ __align__(16) __half Bs[GBN * LDA];

    const int z = blockIdx.z;
    const float* W    = (z == 0) ? Wq : (z == 1) ? Wk : Wv;
    const float* bias = (z == 0) ? bq : (z == 1) ? bk : bv;
    __half* out       = (z == 0) ? g_Q : (z == 1) ? g_K : g_V;
    const float scale = (z == 0) ? 0.125f : 1.0f;

    const int tid  = threadIdx.x;
    const int lane = tid & 31;
    const int wid  = tid >> 5;
    const int bm   = blockIdx.y * GBM;
    const int bn   = blockIdx.x * GBN;
    const int moff = (wid & 3) * 32;
    const int noff = (wid >> 2) * 64;
    const int g    = lane >> 2;
    const int c    = lane & 3;

    const uint32_t as_base = (uint32_t)__cvta_generic_to_shared(As);
    const uint32_t bs_base = (uint32_t)__cvta_generic_to_shared(Bs);
    const int arow = ((lane >> 3) & 1) * 8 + (lane & 7);
    const int acol = (lane >> 4) * 8;
    const int brow = ((lane >> 4) << 3) + (lane & 7);
    const int bcol = ((lane >> 3) & 1) * 8;

    float d[2][8][4];
    #pragma unroll
    for (int mt = 0; mt < 2; mt++)
        #pragma unroll
        for (int nt = 0; nt < 8; nt++)
            #pragma unroll
            for (int e = 0; e < 4; e++) d[mt][nt][e] = 0.f;

    for (int k0 = 0; k0 < H_; k0 += GBK) {
        #pragma unroll
        for (int i = 0; i < 2; i++) {
            int idx = tid + 256 * i;
            int row = idx >> 2, c8 = idx & 3;
            const float4* px = (const float4*)(X + (size_t)(bm + row) * H_ + k0 + c8 * 8);
            float4 v0 = px[0], v1 = px[1];
            __half2 h[4] = { __floats2half2_rn(v0.x, v0.y), __floats2half2_rn(v0.z, v0.w),
                             __floats2half2_rn(v1.x, v1.y), __floats2half2_rn(v1.z, v1.w) };
            *(uint4*)&As[row * LDA + c8 * 8] = *(uint4*)h;
            const float4* pw = (const float4*)(W + (size_t)(bn + row) * H_ + k0 + c8 * 8);
            float4 w0 = pw[0], w1 = pw[1];
            __half2 hw[4] = { __floats2half2_rn(w0.x, w0.y), __floats2half2_rn(w0.z, w0.w),
                              __floats2half2_rn(w1.x, w1.y), __floats2half2_rn(w1.z, w1.w) };
            *(uint4*)&Bs[row * LDA + c8 * 8] = *(uint4*)hw;
        }
        __syncthreads();

        #pragma unroll
        for (int kc = 0; kc < 2; kc++) {
            const int kk = kc * 16;
            uint32_t a[2][4];
            #pragma unroll
            for (int mt = 0; mt < 2; mt++) {
                int row = moff + mt * 16 + arow;
                ldsm4(as_base + (row * LDA + kk + acol) * 2,
                      a[mt][0], a[mt][1], a[mt][2], a[mt][3]);
            }
            #pragma unroll
            for (int np = 0; np < 4; np++) {
                uint32_t b0, b1, b2, b3;
                int row = noff + np * 16 + brow;
                ldsm4(bs_base + (row * LDA + kk + bcol) * 2, b0, b1, b2, b3);
                uint32_t bl[2] = { b0, b1 }, bh[2] = { b2, b3 };
                #pragma unroll
                for (int mt = 0; mt < 2; mt++) {
                    mma_f16(d[mt][2 * np],     a[mt], bl);
                    mma_f16(d[mt][2 * np + 1], a[mt], bh);
                }
            }
        }
        __syncthreads();
    }

    #pragma unroll
    for (int mt = 0; mt < 2; mt++) {
        int row = bm + moff + mt * 16 + g;
        #pragma unroll
        for (int nt = 0; nt < 8; nt++) {
            int col = bn + noff + nt * 8 + 2 * c;
            float2 bv2 = *(const float2*)(bias + col);
            __half2 lo = __floats2half2_rn((d[mt][nt][0] + bv2.x) * scale,
                                           (d[mt][nt][1] + bv2.y) * scale);
            __half2 hi = __floats2half2_rn((d[mt][nt][2] + bv2.x) * scale,
                                           (d[mt][nt][3] + bv2.y) * scale);
            *(__half2*)(out + (size_t)row * H_ + col)       = lo;
            *(__half2*)(out + (size_t)(row + 8) * H_ + col) = hi;
        }
    }
}

// ---------------------------------------------------------------------------
// Flash attention, fp16 mma. Block = 128 threads (4 warps), tile 64x64.
// Warp w owns query rows [w*16, w*16+16). P stays in registers (C-frag of S
// == A-frag packing for PV). Shared stride 72 halves (144B) -> ldmatrix rows
// rotate 1 chunk mod 8 => conflict-free.
// ---------------------------------------------------------------------------
#define LQH 72

__global__ __launch_bounds__(128) void attn_fp16(
    const float* __restrict__ mask, float* __restrict__ out)
{
    __shared__ __align__(16) __half Qs[64 * LQH];
    __shared__ __align__(16) __half Ks[64 * LQH];
    __shared__ __align__(16) __half Vs[64 * LQH];
    __shared__ float Ms[64];

    const int tid  = threadIdx.x;
    const int lane = tid & 31;
    const int wid  = tid >> 5;
    const int qb   = blockIdx.x;
    const int h    = blockIdx.y;
    const int b    = blockIdx.z;
    const int g    = lane >> 2;
    const int c    = lane & 3;
    const int qrow0 = qb * 64 + wid * 16 + g;   // set 0; set 1 = +8

    const uint32_t qs_base = (uint32_t)__cvta_generic_to_shared(Qs);
    const uint32_t ks_base = (uint32_t)__cvta_generic_to_shared(Ks);
    const uint32_t vs_base = (uint32_t)__cvta_generic_to_shared(Vs);
    const int arow = ((lane >> 3) & 1) * 8 + (lane & 7);  // A / V(.trans) row pattern
    const int acol = (lane >> 4) * 8;
    const int brow = ((lane >> 4) << 3) + (lane & 7);     // B(K) row pattern
    const int bcol = ((lane >> 3) & 1) * 8;

    // Stage Q tile (pre-scaled fp16 in g_Q).
    const __half* qg = g_Q + ((size_t)(b * T_) + (size_t)qb * 64) * H_ + h * HD_;
    #pragma unroll
    for (int i = 0; i < 4; i++) {
        int idx = tid + 128 * i;
        int row = idx >> 3, c8 = idx & 7;
        *(uint4*)&Qs[row * LQH + c8 * 8] =
            *(const uint4*)(qg + (size_t)row * H_ + c8 * 8);
    }

    float o[8][4];
    #pragma unroll
    for (int nt = 0; nt < 8; nt++)
        #pragma unroll
        for (int e = 0; e < 4; e++) o[nt][e] = 0.f;
    float m0 = -1e30f, m1 = -1e30f, l0 = 0.f, l1 = 0.f;

    for (int kb = 0; kb <= qb; kb++) {
        __syncthreads();   // prior iteration's readers of Ks/Vs are done
        const __half* kg = g_K + ((size_t)(b * T_) + (size_t)kb * 64) * H_ + h * HD_;
        const __half* vg = g_V + ((size_t)(b * T_) + (size_t)kb * 64) * H_ + h * HD_;
        #pragma unroll
        for (int i = 0; i < 4; i++) {
            int idx = tid + 128 * i;
            int row = idx >> 3, c8 = idx & 7;
            *(uint4*)&Ks[row * LQH + c8 * 8] = *(const uint4*)(kg + (size_t)row * H_ + c8 * 8);
            *(uint4*)&Vs[row * LQH + c8 * 8] = *(const uint4*)(vg + (size_t)row * H_ + c8 * 8);
        }
        if (tid < 64) Ms[tid] = mask[(size_t)b * T_ + kb * 64 + tid];
        __syncthreads();

        // ---- S = Qs Ks^T ----
        float s[8][4];
        #pragma unroll
        for (int nt = 0; nt < 8; nt++)
            #pragma unroll
            for (int e = 0; e < 4; e++) s[nt][e] = 0.f;

        #pragma unroll
        for (int kc = 0; kc < 4; kc++) {
            const int kk = kc * 16;
            uint32_t a[4];
            ldsm4(qs_base + ((wid * 16 + arow) * LQH + kk + acol) * 2,
                  a[0], a[1], a[2], a[3]);
            #pragma unroll
            for (int np = 0; np < 4; np++) {
                uint32_t b0, b1, b2, b3;
                ldsm4(ks_base + ((np * 16 + brow) * LQH + kk + bcol) * 2, b0, b1, b2, b3);
                uint32_t bl[2] = { b0, b1 }, bh[2] = { b2, b3 };
                mma_f16(s[2 * np],     a, bl);
                mma_f16(s[2 * np + 1], a, bh);
            }
        }

        // ---- mask + online softmax ----
        float rmax0 = -1e30f, rmax1 = -1e30f;
        #pragma unroll
        for (int nt = 0; nt < 8; nt++) {
            int lc = nt * 8 + 2 * c;
            float mk0 = Ms[lc], mk1 = Ms[lc + 1];
            s[nt][0] += mk0; s[nt][1] += mk1;
            s[nt][2] += mk0; s[nt][3] += mk1;
            if (kb == qb) {
                int col = kb * 64 + lc;
                if (col     > qrow0)     s[nt][0] = -1e30f;
                if (col + 1 > qrow0)     s[nt][1] = -1e30f;
                if (col     > qrow0 + 8) s[nt][2] = -1e30f;
                if (col + 1 > qrow0 + 8) s[nt][3] = -1e30f;
            }
            rmax0 = fmaxf(rmax0, fmaxf(s[nt][0], s[nt][1]));
            rmax1 = fmaxf(rmax1, fmaxf(s[nt][2], s[nt][3]));
        }
        rmax0 = fmaxf(rmax0, __shfl_xor_sync(0xffffffffu, rmax0, 1));
        rmax0 = fmaxf(rmax0, __shfl_xor_sync(0xffffffffu, rmax0, 2));
        rmax1 = fmaxf(rmax1, __shfl_xor_sync(0xffffffffu, rmax1, 1));
        rmax1 = fmaxf(rmax1, __shfl_xor_sync(0xffffffffu, rmax1, 2));

        float mn0 = fmaxf(m0, rmax0), mn1 = fmaxf(m1, rmax1);
        float cr0 = __expf(m0 - mn0), cr1 = __expf(m1 - mn1);
        m0 = mn0; m1 = mn1;
        l0 *= cr0; l1 *= cr1;

        float ps0 = 0.f, ps1 = 0.f;
        uint32_t ph[8][2];   // P packed fp16: [nt] -> {rows g, g+8} x cols 2c,2c+1
        #pragma unroll
        for (int nt = 0; nt < 8; nt++) {
            float p0 = __expf(s[nt][0] - m0);
            float p1 = __expf(s[nt][1] - m0);
            float p2 = __expf(s[nt][2] - m1);
            float p3 = __expf(s[nt][3] - m1);
            ps0 += p0 + p1; ps1 += p2 + p3;
            __half2 h01 = __floats2half2_rn(p0, p1);
            __half2 h23 = __floats2half2_rn(p2, p3);
            ph[nt][0] = *(uint32_t*)&h01;
            ph[nt][1] = *(uint32_t*)&h23;
            o[nt][0] *= cr0; o[nt][1] *= cr0;
            o[nt][2] *= cr1; o[nt][3] *= cr1;
        }
        ps0 += __shfl_xor_sync(0xffffffffu, ps0, 1);
        ps0 += __shfl_xor_sync(0xffffffffu, ps0, 2);
        ps1 += __shfl_xor_sync(0xffffffffu, ps1, 1);
        ps1 += __shfl_xor_sync(0xffffffffu, ps1, 2);
        l0 += ps0; l1 += ps1;

        // ---- O += P V  (P direct from registers; V via ldmatrix.trans) ----
        #pragma unroll
        for (int jc = 0; jc < 4; jc++) {
            uint32_t a[4] = { ph[2 * jc][0], ph[2 * jc][1],
                              ph[2 * jc + 1][0], ph[2 * jc + 1][1] };
            #pragma unroll
            for (int dp = 0; dp < 4; dp++) {
                uint32_t b0, b1, b2, b3;
                ldsm4t(vs_base + ((jc * 16 + arow) * LQH + dp * 16 + acol) * 2,
                       b0, b1, b2, b3);
                uint32_t bl[2] = { b0, b1 }, bh[2] = { b2, b3 };
                mma_f16(o[2 * dp],     a, bl);
                mma_f16(o[2 * dp + 1], a, bh);
            }
        }
    }

    // ---- epilogue ----
    float inv0 = 1.f / l0, inv1 = 1.f / l1;
    float* og = out + ((size_t)(b * T_) + (size_t)qb * 64 + wid * 16 + g) * H_ + h * HD_;
    #pragma unroll
    for (int nt = 0; nt < 8; nt++) {
        int lc = nt * 8 + 2 * c;
        float2 w0, w1;
        w0.x = o[nt][0] * inv0; w0.y = o[nt][1] * inv0;
        w1.x = o[nt][2] * inv1; w1.y = o[nt][3] * inv1;
        *(float2*)(og + lc)          = w0;
        *(float2*)(og + 8 * H_ + lc) = w1;
    }
}

// ---------------------------------------------------------------------------
// Launch
// ---------------------------------------------------------------------------
extern "C" void kernel_launch(void* const* d_in, const int* in_sizes, int n_in,
                              void* d_out, int out_size)
{
    const float* x    = (const float*)d_in[0];
    const float* mask = (const float*)d_in[1];
    const float* Wq   = (const float*)d_in[2];
    const float* bq   = (const float*)d_in[3];
    const float* Wk   = (const float*)d_in[4];
    const float* bk   = (const float*)d_in[5];
    const float* Wv   = (const float*)d_in[6];
    const float* bv   = (const float*)d_in[7];
    float* out = (float*)d_out;

    dim3 ggrid(H_ / GBN, M_ / GBM, 3);   // (8, 64, 3) fused Q/K/V
    qkv_gemm_fp16<<<ggrid, 256>>>(x, Wq, bq, Wk, bk, Wv, bv);

    dim3 agrid(T_ / 64, NH_, B_);        // (32, 16, 4)
    attn_fp16<<<agrid, 128>>>(mask, out);
}

// round 7
// speedup vs baseline: 8.3331x; 1.3144x over previous
#include <cuda_runtime.h>
#include <cuda_fp16.h>
#include <stdint.h>

#define B_  4
#define T_  2048
#define H_  1024
#define NH_ 16
#define HD_ 64
#define M_  (B_ * T_)   // 8192

// fp16 scratch: projected Q(pre-scaled)/K/V, converted X and W.
__device__ __half g_Q[M_ * H_];
__device__ __half g_K[M_ * H_];
__device__ __half g_V[M_ * H_];
__device__ __half g_X16[M_ * H_];
__device__ __half g_W16[3 * H_ * H_];

// ===========================================================================
// PTX helpers (mma.sync / ldmatrix / cp.async only — no tcgen05: the harness
// compiles to plain sm_100, which lacks arch-specific 'a' features)
// ===========================================================================
__device__ __forceinline__ void mma_f16(float d[4], const uint32_t a[4], const uint32_t b[2]) {
    asm volatile(
        "mma.sync.aligned.m16n8k16.row.col.f32.f16.f16.f32 "
        "{%0,%1,%2,%3}, {%4,%5,%6,%7}, {%8,%9}, {%0,%1,%2,%3};\n"
        : "+f"(d[0]), "+f"(d[1]), "+f"(d[2]), "+f"(d[3])
        : "r"(a[0]), "r"(a[1]), "r"(a[2]), "r"(a[3]), "r"(b[0]), "r"(b[1]));
}
__device__ __forceinline__ void ldsm4(uint32_t addr, uint32_t &r0, uint32_t &r1,
                                      uint32_t &r2, uint32_t &r3) {
    asm volatile("ldmatrix.sync.aligned.m8n8.x4.shared.b16 {%0,%1,%2,%3}, [%4];"
                 : "=r"(r0), "=r"(r1), "=r"(r2), "=r"(r3) : "r"(addr));
}
__device__ __forceinline__ void ldsm4t(uint32_t addr, uint32_t &r0, uint32_t &r1,
                                       uint32_t &r2, uint32_t &r3) {
    asm volatile("ldmatrix.sync.aligned.m8n8.x4.trans.shared.b16 {%0,%1,%2,%3}, [%4];"
                 : "=r"(r0), "=r"(r1), "=r"(r2), "=r"(r3) : "r"(addr));
}
__device__ __forceinline__ void cp16(uint32_t saddr, const void* gaddr) {
    asm volatile("cp.async.cg.shared.global [%0], [%1], 16;" :: "r"(saddr), "l"(gaddr));
}
__device__ __forceinline__ void cp4(uint32_t saddr, const void* gaddr) {
    asm volatile("cp.async.ca.shared.global [%0], [%1], 4;" :: "r"(saddr), "l"(gaddr));
}
__device__ __forceinline__ void cp_commit() {
    asm volatile("cp.async.commit_group;" ::: "memory");
}
template <int N>
__device__ __forceinline__ void cp_wait() {
    asm volatile("cp.async.wait_group %0;" :: "n"(N) : "memory");
}

// ===========================================================================
// fp32 -> fp16 bulk convert (8 elems / thread)
// ===========================================================================
__global__ __launch_bounds__(256) void cvt32to16(
    const float* __restrict__ src, __half* __restrict__ dst, int n8)
{
    int i = blockIdx.x * blockDim.x + threadIdx.x;
    if (i < n8) {
        const float4* s4 = (const float4*)src + (size_t)i * 2;
        float4 a = s4[0], b = s4[1];
        __half2 h[4] = { __floats2half2_rn(a.x, a.y), __floats2half2_rn(a.z, a.w),
                         __floats2half2_rn(b.x, b.y), __floats2half2_rn(b.z, b.w) };
        *((uint4*)dst + i) = *(uint4*)h;
    }
}

// ===========================================================================
// QKV GEMM, fp16 mma.sync + cp.async double buffering.
// out[m,n] = (sum_k X16[m,k]*W16[n,k] + bias[n]) * scale, fp16 out.
// 128x128 tiles, K-chunks of 64, 2 stages. 8 warps (4m x 2n), warp 32x64.
// Smem stride 72 halves (144B) -> ldmatrix rows rotate 1 unit mod 8.
// ===========================================================================
#define GLD    72
#define GSTG   (128 * GLD)                 // halves per operand per stage
#define NCHUNK 16
#define GEMM_SMEM (4 * GSTG * 2)           // 73728 bytes

__global__ __launch_bounds__(256) void qkv_gemm_fp16(
    const float* __restrict__ bq, const float* __restrict__ bk,
    const float* __restrict__ bv)
{
    extern __shared__ __align__(16) __half smh[];
    const uint32_t sb = (uint32_t)__cvta_generic_to_shared(smh);

    const int z = blockIdx.z;
    const __half* Wp  = g_W16 + (size_t)z * H_ * H_;
    const float* bias = (z == 0) ? bq : (z == 1) ? bk : bv;
    __half* out       = (z == 0) ? g_Q : (z == 1) ? g_K : g_V;
    const float scale = (z == 0) ? 0.125f : 1.0f;

    const int tid  = threadIdx.x;
    const int lane = tid & 31;
    const int wid  = tid >> 5;
    const int bm   = blockIdx.y * 128;
    const int bn   = blockIdx.x * 128;
    const int moff = (wid & 3) * 32;
    const int noff = (wid >> 2) * 64;
    const int g    = lane >> 2;
    const int c    = lane & 3;
    const int arow = ((lane >> 3) & 1) * 8 + (lane & 7);
    const int acol = (lane >> 4) * 8;
    const int brow = ((lane >> 4) << 3) + (lane & 7);
    const int bcol = ((lane >> 3) & 1) * 8;

    // Per-thread copy coordinates: 1024 16B-chunks per operand, 4 per thread.
    const int crow = tid >> 1;            // via u = tid + 256*i: row = u>>3
    // (computed inline below)

    float d[2][8][4];
    #pragma unroll
    for (int mt = 0; mt < 2; mt++)
        #pragma unroll
        for (int nt = 0; nt < 8; nt++)
            #pragma unroll
            for (int e = 0; e < 4; e++) d[mt][nt][e] = 0.f;
    (void)crow;

    // issue stage kc into slot s
    auto issue = [&](int kc, int s) {
        const int k0 = kc * 64;
        #pragma unroll
        for (int i = 0; i < 4; i++) {
            int u = tid + 256 * i;
            int row = u >> 3, c8 = u & 7;
            cp16(sb + (s * GSTG + row * GLD + c8 * 8) * 2,
                 g_X16 + (size_t)(bm + row) * H_ + k0 + c8 * 8);
            cp16(sb + ((2 + s) * GSTG + row * GLD + c8 * 8) * 2,
                 Wp + (size_t)(bn + row) * H_ + k0 + c8 * 8);
        }
        cp_commit();
    };

    issue(0, 0);
    issue(1, 1);

    for (int kc = 0; kc < NCHUNK; kc++) {
        const int s = kc & 1;
        if (kc < NCHUNK - 1) cp_wait<1>(); else cp_wait<0>();
        __syncthreads();

        const uint32_t ab = sb + (s * GSTG) * 2;
        const uint32_t bb = sb + ((2 + s) * GSTG) * 2;
        #pragma unroll
        for (int kcc = 0; kcc < 4; kcc++) {
            const int kk = kcc * 16;
            uint32_t a[2][4];
            #pragma unroll
            for (int mt = 0; mt < 2; mt++) {
                int row = moff + mt * 16 + arow;
                ldsm4(ab + (row * GLD + kk + acol) * 2,
                      a[mt][0], a[mt][1], a[mt][2], a[mt][3]);
            }
            #pragma unroll
            for (int np = 0; np < 4; np++) {
                uint32_t b0, b1, b2, b3;
                int row = noff + np * 16 + brow;
                ldsm4(bb + (row * GLD + kk + bcol) * 2, b0, b1, b2, b3);
                uint32_t bl[2] = { b0, b1 }, bh[2] = { b2, b3 };
                #pragma unroll
                for (int mt = 0; mt < 2; mt++) {
                    mma_f16(d[mt][2 * np],     a[mt], bl);
                    mma_f16(d[mt][2 * np + 1], a[mt], bh);
                }
            }
        }
        __syncthreads();
        if (kc + 2 < NCHUNK) issue(kc + 2, s);
    }

    // Epilogue: bias (global, L2-resident) + scale, fp16 stores.
    #pragma unroll
    for (int mt = 0; mt < 2; mt++) {
        int row = bm + moff + mt * 16 + g;
        #pragma unroll
        for (int nt = 0; nt < 8; nt++) {
            int col = bn + noff + nt * 8 + 2 * c;
            float2 bv2 = *(const float2*)(bias + col);
            __half2 lo = __floats2half2_rn((d[mt][nt][0] + bv2.x) * scale,
                                           (d[mt][nt][1] + bv2.y) * scale);
            __half2 hi = __floats2half2_rn((d[mt][nt][2] + bv2.x) * scale,
                                           (d[mt][nt][3] + bv2.y) * scale);
            *(__half2*)(out + (size_t)row * H_ + col)       = lo;
            *(__half2*)(out + (size_t)(row + 8) * H_ + col) = hi;
        }
    }
}

// ===========================================================================
// Flash attention, fp16 mma.sync + cp.async double-buffered K/V tiles.
// Block = 128 threads (4 warps), tile 64x64, warp owns 16 query rows.
// P stays in registers (S C-frag == PV A-frag packing). Stride 72 halves.
// ===========================================================================
#define LQH 72

__global__ __launch_bounds__(128) void attn_fp16(
    const float* __restrict__ mask, float* __restrict__ out)
{
    __shared__ __align__(16) __half Qs[64 * LQH];
    __shared__ __align__(16) __half Ks[2][64 * LQH];
    __shared__ __align__(16) __half Vs[2][64 * LQH];
    __shared__ float Ms[2][64];

    const int tid  = threadIdx.x;
    const int lane = tid & 31;
    const int wid  = tid >> 5;
    const int qb   = blockIdx.x;
    const int h    = blockIdx.y;
    const int b    = blockIdx.z;
    const int g    = lane >> 2;
    const int c    = lane & 3;
    const int qrow0 = qb * 64 + wid * 16 + g;

    const uint32_t qs_base = (uint32_t)__cvta_generic_to_shared(Qs);
    const uint32_t ks_base = (uint32_t)__cvta_generic_to_shared(&Ks[0][0]);
    const uint32_t vs_base = (uint32_t)__cvta_generic_to_shared(&Vs[0][0]);
    const uint32_t ms_base = (uint32_t)__cvta_generic_to_shared(&Ms[0][0]);
    const int arow = ((lane >> 3) & 1) * 8 + (lane & 7);
    const int acol = (lane >> 4) * 8;
    const int brow = ((lane >> 4) << 3) + (lane & 7);
    const int bcol = ((lane >> 3) & 1) * 8;

    const size_t hdoff = (size_t)(b * T_) * H_ + h * HD_;
    const __half* kgb = g_K + hdoff;
    const __half* vgb = g_V + hdoff;

    auto issue = [&](int kb, int buf) {
        const __half* kg = kgb + (size_t)kb * 64 * H_;
        const __half* vg = vgb + (size_t)kb * 64 * H_;
        const uint32_t koff = ks_base + buf * (64 * LQH * 2);
        const uint32_t voff = vs_base + buf * (64 * LQH * 2);
        #pragma unroll
        for (int i = 0; i < 4; i++) {
            int u = tid + 128 * i;
            int row = u >> 3, c8 = u & 7;
            cp16(koff + (row * LQH + c8 * 8) * 2, kg + (size_t)row * H_ + c8 * 8);
            cp16(voff + (row * LQH + c8 * 8) * 2, vg + (size_t)row * H_ + c8 * 8);
        }
        if (tid < 64)
            cp4(ms_base + (buf * 64 + tid) * 4, mask + (size_t)b * T_ + kb * 64 + tid);
        cp_commit();
    };

    // Stage Q (plain loads) + prefetch tile 0.
    const __half* qg = g_Q + hdoff + (size_t)qb * 64 * H_;
    issue(0, 0);
    #pragma unroll
    for (int i = 0; i < 4; i++) {
        int idx = tid + 128 * i;
        int row = idx >> 3, c8 = idx & 7;
        *(uint4*)&Qs[row * LQH + c8 * 8] =
            *(const uint4*)(qg + (size_t)row * H_ + c8 * 8);
    }

    float o[8][4];
    #pragma unroll
    for (int nt = 0; nt < 8; nt++)
        #pragma unroll
        for (int e = 0; e < 4; e++) o[nt][e] = 0.f;
    float m0 = -1e30f, m1 = -1e30f, l0 = 0.f, l1 = 0.f;

    for (int kb = 0; kb <= qb; kb++) {
        const int buf = kb & 1;
        if (kb < qb) { issue(kb + 1, buf ^ 1); cp_wait<1>(); }
        else         { cp_wait<0>(); }
        __syncthreads();

        const uint32_t kbb = ks_base + buf * (64 * LQH * 2);
        const uint32_t vbb = vs_base + buf * (64 * LQH * 2);
        const float* MsB = Ms[buf];

        // ---- S = Qs Ks^T ----
        float s[8][4];
        #pragma unroll
        for (int nt = 0; nt < 8; nt++)
            #pragma unroll
            for (int e = 0; e < 4; e++) s[nt][e] = 0.f;

        #pragma unroll
        for (int kc = 0; kc < 4; kc++) {
            const int kk = kc * 16;
            uint32_t a[4];
            ldsm4(qs_base + ((wid * 16 + arow) * LQH + kk + acol) * 2,
                  a[0], a[1], a[2], a[3]);
            #pragma unroll
            for (int np = 0; np < 4; np++) {
                uint32_t b0, b1, b2, b3;
                ldsm4(kbb + ((np * 16 + brow) * LQH + kk + bcol) * 2, b0, b1, b2, b3);
                uint32_t bl[2] = { b0, b1 }, bh[2] = { b2, b3 };
                mma_f16(s[2 * np],     a, bl);
                mma_f16(s[2 * np + 1], a, bh);
            }
        }

        // ---- mask + online softmax ----
        float rmax0 = -1e30f, rmax1 = -1e30f;
        #pragma unroll
        for (int nt = 0; nt < 8; nt++) {
            int lc = nt * 8 + 2 * c;
            float mk0 = MsB[lc], mk1 = MsB[lc + 1];
            s[nt][0] += mk0; s[nt][1] += mk1;
            s[nt][2] += mk0; s[nt][3] += mk1;
            if (kb == qb) {
                int col = kb * 64 + lc;
                if (col     > qrow0)     s[nt][0] = -1e30f;
                if (col + 1 > qrow0)     s[nt][1] = -1e30f;
                if (col     > qrow0 + 8) s[nt][2] = -1e30f;
                if (col + 1 > qrow0 + 8) s[nt][3] = -1e30f;
            }
            rmax0 = fmaxf(rmax0, fmaxf(s[nt][0], s[nt][1]));
            rmax1 = fmaxf(rmax1, fmaxf(s[nt][2], s[nt][3]));
        }
        rmax0 = fmaxf(rmax0, __shfl_xor_sync(0xffffffffu, rmax0, 1));
        rmax0 = fmaxf(rmax0, __shfl_xor_sync(0xffffffffu, rmax0, 2));
        rmax1 = fmaxf(rmax1, __shfl_xor_sync(0xffffffffu, rmax1, 1));
        rmax1 = fmaxf(rmax1, __shfl_xor_sync(0xffffffffu, rmax1, 2));

        float mn0 = fmaxf(m0, rmax0), mn1 = fmaxf(m1, rmax1);
        float cr0 = __expf(m0 - mn0), cr1 = __expf(m1 - mn1);
        m0 = mn0; m1 = mn1;
        l0 *= cr0; l1 *= cr1;

        float ps0 = 0.f, ps1 = 0.f;
        uint32_t ph[8][2];
        #pragma unroll
        for (int nt = 0; nt < 8; nt++) {
            float p0 = __expf(s[nt][0] - m0);
            float p1 = __expf(s[nt][1] - m0);
            float p2 = __expf(s[nt][2] - m1);
            float p3 = __expf(s[nt][3] - m1);
            ps0 += p0 + p1; ps1 += p2 + p3;
            __half2 h01 = __floats2half2_rn(p0, p1);
            __half2 h23 = __floats2half2_rn(p2, p3);
            ph[nt][0] = *(uint32_t*)&h01;
            ph[nt][1] = *(uint32_t*)&h23;
            o[nt][0] *= cr0; o[nt][1] *= cr0;
            o[nt][2] *= cr1; o[nt][3] *= cr1;
        }
        ps0 += __shfl_xor_sync(0xffffffffu, ps0, 1);
        ps0 += __shfl_xor_sync(0xffffffffu, ps0, 2);
        ps1 += __shfl_xor_sync(0xffffffffu, ps1, 1);
        ps1 += __shfl_xor_sync(0xffffffffu, ps1, 2);
        l0 += ps0; l1 += ps1;

        // ---- O += P V ----
        #pragma unroll
        for (int jc = 0; jc < 4; jc++) {
            uint32_t a[4] = { ph[2 * jc][0], ph[2 * jc][1],
                              ph[2 * jc + 1][0], ph[2 * jc + 1][1] };
            #pragma unroll
            for (int dp = 0; dp < 4; dp++) {
                uint32_t b0, b1, b2, b3;
                ldsm4t(vbb + ((jc * 16 + arow) * LQH + dp * 16 + acol) * 2,
                       b0, b1, b2, b3);
                uint32_t bl[2] = { b0, b1 }, bh[2] = { b2, b3 };
                mma_f16(o[2 * dp],     a, bl);
                mma_f16(o[2 * dp + 1], a, bh);
            }
        }
        __syncthreads();   // all warps done reading buf before it is re-filled
    }

    float inv0 = 1.f / l0, inv1 = 1.f / l1;
    float* og = out + ((size_t)(b * T_) + (size_t)qb * 64 + wid * 16 + g) * H_ + h * HD_;
    #pragma unroll
    for (int nt = 0; nt < 8; nt++) {
        int lc = nt * 8 + 2 * c;
        float2 w0, w1;
        w0.x = o[nt][0] * inv0; w0.y = o[nt][1] * inv0;
        w1.x = o[nt][2] * inv1; w1.y = o[nt][3] * inv1;
        *(float2*)(og + lc)          = w0;
        *(float2*)(og + 8 * H_ + lc) = w1;
    }
}

// ===========================================================================
// Launch
// ===========================================================================
extern "C" void kernel_launch(void* const* d_in, const int* in_sizes, int n_in,
                              void* d_out, int out_size)
{
    const float* x    = (const float*)d_in[0];
    const float* mask = (const float*)d_in[1];
    const float* Wq   = (const float*)d_in[2];
    const float* bq   = (const float*)d_in[3];
    const float* Wk   = (const float*)d_in[4];
    const float* bk   = (const float*)d_in[5];
    const float* Wv   = (const float*)d_in[6];
    const float* bv   = (const float*)d_in[7];
    float* out = (float*)d_out;

    __half *X16p, *W16p;
    cudaGetSymbolAddress((void**)&X16p, g_X16);
    cudaGetSymbolAddress((void**)&W16p, g_W16);

    cudaFuncSetAttribute(qkv_gemm_fp16, cudaFuncAttributeMaxDynamicSharedMemorySize,
                         GEMM_SMEM);

    cvt32to16<<<(M_ * H_ / 8 + 255) / 256, 256>>>(x, X16p, M_ * H_ / 8);
    cvt32to16<<<(H_ * H_ / 8 + 255) / 256, 256>>>(Wq, W16p,               H_ * H_ / 8);
    cvt32to16<<<(H_ * H_ / 8 + 255) / 256, 256>>>(Wk, W16p + H_ * H_,     H_ * H_ / 8);
    cvt32to16<<<(H_ * H_ / 8 + 255) / 256, 256>>>(Wv, W16p + 2 * H_ * H_, H_ * H_ / 8);

    dim3 ggrid(H_ / 128, M_ / 128, 3);   // (8, 64, 3)
    qkv_gemm_fp16<<<ggrid, 256, GEMM_SMEM>>>(bq, bk, bv);

    dim3 agrid(T_ / 64, NH_, B_);        // (32, 16, 4)
    attn_fp16<<<agrid, 128>>>(mask, out);
}

// round 8
// speedup vs baseline: 8.4588x; 1.0151x over previous
#include <cuda_runtime.h>
#include <cuda_fp16.h>
#include <stdint.h>

#define B_  4
#define T_  2048
#define H_  1024
#define NH_ 16
#define HD_ 64
#define M_  (B_ * T_)   // 8192

#define LOG2E 1.4426950408889634f

// fp16 scratch: projected Q(pre-scaled by 0.125*log2e)/K/V, converted X and W.
__device__ __half g_Q[M_ * H_];
__device__ __half g_K[M_ * H_];
__device__ __half g_V[M_ * H_];
__device__ __half g_X16[M_ * H_];
__device__ __half g_W16[3 * H_ * H_];

// ===========================================================================
// PTX helpers (mma.sync / ldmatrix / cp.async only — harness targets sm_100,
// no 'a'-suffix features, so tcgen05 is unavailable)
// ===========================================================================
__device__ __forceinline__ void mma_f16(float d[4], const uint32_t a[4], const uint32_t b[2]) {
    asm volatile(
        "mma.sync.aligned.m16n8k16.row.col.f32.f16.f16.f32 "
        "{%0,%1,%2,%3}, {%4,%5,%6,%7}, {%8,%9}, {%0,%1,%2,%3};\n"
        : "+f"(d[0]), "+f"(d[1]), "+f"(d[2]), "+f"(d[3])
        : "r"(a[0]), "r"(a[1]), "r"(a[2]), "r"(a[3]), "r"(b[0]), "r"(b[1]));
}
__device__ __forceinline__ void ldsm4(uint32_t addr, uint32_t &r0, uint32_t &r1,
                                      uint32_t &r2, uint32_t &r3) {
    asm volatile("ldmatrix.sync.aligned.m8n8.x4.shared.b16 {%0,%1,%2,%3}, [%4];"
                 : "=r"(r0), "=r"(r1), "=r"(r2), "=r"(r3) : "r"(addr));
}
__device__ __forceinline__ void ldsm4t(uint32_t addr, uint32_t &r0, uint32_t &r1,
                                       uint32_t &r2, uint32_t &r3) {
    asm volatile("ldmatrix.sync.aligned.m8n8.x4.trans.shared.b16 {%0,%1,%2,%3}, [%4];"
                 : "=r"(r0), "=r"(r1), "=r"(r2), "=r"(r3) : "r"(addr));
}
__device__ __forceinline__ void cp16(uint32_t saddr, const void* gaddr) {
    asm volatile("cp.async.cg.shared.global [%0], [%1], 16;" :: "r"(saddr), "l"(gaddr));
}
__device__ __forceinline__ void cp4(uint32_t saddr, const void* gaddr) {
    asm volatile("cp.async.ca.shared.global [%0], [%1], 4;" :: "r"(saddr), "l"(gaddr));
}
__device__ __forceinline__ void cp_commit() {
    asm volatile("cp.async.commit_group;" ::: "memory");
}
template <int N>
__device__ __forceinline__ void cp_wait() {
    asm volatile("cp.async.wait_group %0;" :: "n"(N) : "memory");
}

// ===========================================================================
// fp32 -> fp16 bulk convert (8 elems / thread)
// ===========================================================================
__global__ __launch_bounds__(256) void cvt32to16(
    const float* __restrict__ src, __half* __restrict__ dst, int n8)
{
    int i = blockIdx.x * blockDim.x + threadIdx.x;
    if (i < n8) {
        const float4* s4 = (const float4*)src + (size_t)i * 2;
        float4 a = s4[0], b = s4[1];
        __half2 h[4] = { __floats2half2_rn(a.x, a.y), __floats2half2_rn(a.z, a.w),
                         __floats2half2_rn(b.x, b.y), __floats2half2_rn(b.z, b.w) };
        *((uint4*)dst + i) = *(uint4*)h;
    }
}

// ===========================================================================
// QKV GEMM, fp16 mma.sync + cp.async double buffering (unchanged from R7).
// Q gets scale = 0.125 * LOG2E (softmax moved to exp2 domain).
// ===========================================================================
#define GLD    72
#define GSTG   (128 * GLD)
#define NCHUNK 16
#define GEMM_SMEM (4 * GSTG * 2)           // 73728 bytes

__global__ __launch_bounds__(256) void qkv_gemm_fp16(
    const float* __restrict__ bq, const float* __restrict__ bk,
    const float* __restrict__ bv)
{
    extern __shared__ __align__(16) __half smh[];
    const uint32_t sb = (uint32_t)__cvta_generic_to_shared(smh);

    const int z = blockIdx.z;
    const __half* Wp  = g_W16 + (size_t)z * H_ * H_;
    const float* bias = (z == 0) ? bq : (z == 1) ? bk : bv;
    __half* out       = (z == 0) ? g_Q : (z == 1) ? g_K : g_V;
    const float scale = (z == 0) ? 0.125f * LOG2E : 1.0f;

    const int tid  = threadIdx.x;
    const int lane = tid & 31;
    const int wid  = tid >> 5;
    const int bm   = blockIdx.y * 128;
    const int bn   = blockIdx.x * 128;
    const int moff = (wid & 3) * 32;
    const int noff = (wid >> 2) * 64;
    const int g    = lane >> 2;
    const int c    = lane & 3;
    const int arow = ((lane >> 3) & 1) * 8 + (lane & 7);
    const int acol = (lane >> 4) * 8;
    const int brow = ((lane >> 4) << 3) + (lane & 7);
    const int bcol = ((lane >> 3) & 1) * 8;

    float d[2][8][4];
    #pragma unroll
    for (int mt = 0; mt < 2; mt++)
        #pragma unroll
        for (int nt = 0; nt < 8; nt++)
            #pragma unroll
            for (int e = 0; e < 4; e++) d[mt][nt][e] = 0.f;

    auto issue = [&](int kc, int s) {
        const int k0 = kc * 64;
        #pragma unroll
        for (int i = 0; i < 4; i++) {
            int u = tid + 256 * i;
            int row = u >> 3, c8 = u & 7;
            cp16(sb + (s * GSTG + row * GLD + c8 * 8) * 2,
                 g_X16 + (size_t)(bm + row) * H_ + k0 + c8 * 8);
            cp16(sb + ((2 + s) * GSTG + row * GLD + c8 * 8) * 2,
                 Wp + (size_t)(bn + row) * H_ + k0 + c8 * 8);
        }
        cp_commit();
    };

    issue(0, 0);
    issue(1, 1);

    for (int kc = 0; kc < NCHUNK; kc++) {
        const int s = kc & 1;
        if (kc < NCHUNK - 1) cp_wait<1>(); else cp_wait<0>();
        __syncthreads();

        const uint32_t ab = sb + (s * GSTG) * 2;
        const uint32_t bb = sb + ((2 + s) * GSTG) * 2;
        #pragma unroll
        for (int kcc = 0; kcc < 4; kcc++) {
            const int kk = kcc * 16;
            uint32_t a[2][4];
            #pragma unroll
            for (int mt = 0; mt < 2; mt++) {
                int row = moff + mt * 16 + arow;
                ldsm4(ab + (row * GLD + kk + acol) * 2,
                      a[mt][0], a[mt][1], a[mt][2], a[mt][3]);
            }
            #pragma unroll
            for (int np = 0; np < 4; np++) {
                uint32_t b0, b1, b2, b3;
                int row = noff + np * 16 + brow;
                ldsm4(bb + (row * GLD + kk + bcol) * 2, b0, b1, b2, b3);
                uint32_t bl[2] = { b0, b1 }, bh[2] = { b2, b3 };
                #pragma unroll
                for (int mt = 0; mt < 2; mt++) {
                    mma_f16(d[mt][2 * np],     a[mt], bl);
                    mma_f16(d[mt][2 * np + 1], a[mt], bh);
                }
            }
        }
        __syncthreads();
        if (kc + 2 < NCHUNK) issue(kc + 2, s);
    }

    #pragma unroll
    for (int mt = 0; mt < 2; mt++) {
        int row = bm + moff + mt * 16 + g;
        #pragma unroll
        for (int nt = 0; nt < 8; nt++) {
            int col = bn + noff + nt * 8 + 2 * c;
            float2 bv2 = *(const float2*)(bias + col);
            __half2 lo = __floats2half2_rn((d[mt][nt][0] + bv2.x) * scale,
                                           (d[mt][nt][1] + bv2.y) * scale);
            __half2 hi = __floats2half2_rn((d[mt][nt][2] + bv2.x) * scale,
                                           (d[mt][nt][3] + bv2.y) * scale);
            *(__half2*)(out + (size_t)row * H_ + col)       = lo;
            *(__half2*)(out + (size_t)(row + 8) * H_ + col) = hi;
        }
    }
}

// ===========================================================================
// Flash attention. Changes vs R7:
//  - qb reversed (heavy blocks first -> packed waves)
//  - Q fragments hoisted to registers (loaded once)
//  - softmax in exp2 domain (Q pre-scaled by log2e; mask scaled at use)
// ===========================================================================
#define LQH 72

__global__ __launch_bounds__(128) void attn_fp16(
    const float* __restrict__ mask, float* __restrict__ out)
{
    __shared__ __align__(16) __half Qs[64 * LQH];
    __shared__ __align__(16) __half Ks[2][64 * LQH];
    __shared__ __align__(16) __half Vs[2][64 * LQH];
    __shared__ float Ms[2][64];

    const int tid  = threadIdx.x;
    const int lane = tid & 31;
    const int wid  = tid >> 5;
    const int qb   = (T_ / 64 - 1) - blockIdx.x;   // reversed: heavy first
    const int h    = blockIdx.y;
    const int b    = blockIdx.z;
    const int g    = lane >> 2;
    const int c    = lane & 3;
    const int qrow0 = qb * 64 + wid * 16 + g;

    const uint32_t qs_base = (uint32_t)__cvta_generic_to_shared(Qs);
    const uint32_t ks_base = (uint32_t)__cvta_generic_to_shared(&Ks[0][0]);
    const uint32_t vs_base = (uint32_t)__cvta_generic_to_shared(&Vs[0][0]);
    const uint32_t ms_base = (uint32_t)__cvta_generic_to_shared(&Ms[0][0]);
    const int arow = ((lane >> 3) & 1) * 8 + (lane & 7);
    const int acol = (lane >> 4) * 8;
    const int brow = ((lane >> 4) << 3) + (lane & 7);
    const int bcol = ((lane >> 3) & 1) * 8;

    const size_t hdoff = (size_t)(b * T_) * H_ + h * HD_;
    const __half* kgb = g_K + hdoff;
    const __half* vgb = g_V + hdoff;

    auto issue = [&](int kb, int buf) {
        const __half* kg = kgb + (size_t)kb * 64 * H_;
        const __half* vg = vgb + (size_t)kb * 64 * H_;
        const uint32_t koff = ks_base + buf * (64 * LQH * 2);
        const uint32_t voff = vs_base + buf * (64 * LQH * 2);
        #pragma unroll
        for (int i = 0; i < 4; i++) {
            int u = tid + 128 * i;
            int row = u >> 3, c8 = u & 7;
            cp16(koff + (row * LQH + c8 * 8) * 2, kg + (size_t)row * H_ + c8 * 8);
            cp16(voff + (row * LQH + c8 * 8) * 2, vg + (size_t)row * H_ + c8 * 8);
        }
        if (tid < 64)
            cp4(ms_base + (buf * 64 + tid) * 4, mask + (size_t)b * T_ + kb * 64 + tid);
        cp_commit();
    };

    // Stage Q + prefetch tile 0.
    const __half* qg = g_Q + hdoff + (size_t)qb * 64 * H_;
    issue(0, 0);
    #pragma unroll
    for (int i = 0; i < 4; i++) {
        int idx = tid + 128 * i;
        int row = idx >> 3, c8 = idx & 7;
        *(uint4*)&Qs[row * LQH + c8 * 8] =
            *(const uint4*)(qg + (size_t)row * H_ + c8 * 8);
    }
    __syncthreads();   // Qs visible to all warps

    // Hoist Q fragments: qa[kc][0..3], kc = K-dim chunk of 16.
    uint32_t qa[4][4];
    #pragma unroll
    for (int kc = 0; kc < 4; kc++)
        ldsm4(qs_base + ((wid * 16 + arow) * LQH + kc * 16 + acol) * 2,
              qa[kc][0], qa[kc][1], qa[kc][2], qa[kc][3]);

    float o[8][4];
    #pragma unroll
    for (int nt = 0; nt < 8; nt++)
        #pragma unroll
        for (int e = 0; e < 4; e++) o[nt][e] = 0.f;
    float m0 = -1e30f, m1 = -1e30f, l0 = 0.f, l1 = 0.f;

    for (int kb = 0; kb <= qb; kb++) {
        const int buf = kb & 1;
        if (kb < qb) { issue(kb + 1, buf ^ 1); cp_wait<1>(); }
        else         { cp_wait<0>(); }
        __syncthreads();

        const uint32_t kbb = ks_base + buf * (64 * LQH * 2);
        const uint32_t vbb = vs_base + buf * (64 * LQH * 2);
        const float* MsB = Ms[buf];

        // ---- S = Qs Ks^T  (log2-domain scores) ----
        float s[8][4];
        #pragma unroll
        for (int nt = 0; nt < 8; nt++)
            #pragma unroll
            for (int e = 0; e < 4; e++) s[nt][e] = 0.f;

        #pragma unroll
        for (int kc = 0; kc < 4; kc++) {
            const int kk = kc * 16;
            #pragma unroll
            for (int np = 0; np < 4; np++) {
                uint32_t b0, b1, b2, b3;
                ldsm4(kbb + ((np * 16 + brow) * LQH + kk + bcol) * 2, b0, b1, b2, b3);
                uint32_t bl[2] = { b0, b1 }, bh[2] = { b2, b3 };
                mma_f16(s[2 * np],     qa[kc], bl);
                mma_f16(s[2 * np + 1], qa[kc], bh);
            }
        }

        // ---- mask + online softmax (exp2) ----
        float rmax0 = -1e30f, rmax1 = -1e30f;
        #pragma unroll
        for (int nt = 0; nt < 8; nt++) {
            int lc = nt * 8 + 2 * c;
            float mk0 = MsB[lc] * LOG2E, mk1 = MsB[lc + 1] * LOG2E;
            s[nt][0] += mk0; s[nt][1] += mk1;
            s[nt][2] += mk0; s[nt][3] += mk1;
            if (kb == qb) {
                int col = kb * 64 + lc;
                if (col     > qrow0)     s[nt][0] = -1e30f;
                if (col + 1 > qrow0)     s[nt][1] = -1e30f;
                if (col     > qrow0 + 8) s[nt][2] = -1e30f;
                if (col + 1 > qrow0 + 8) s[nt][3] = -1e30f;
            }
            rmax0 = fmaxf(rmax0, fmaxf(s[nt][0], s[nt][1]));
            rmax1 = fmaxf(rmax1, fmaxf(s[nt][2], s[nt][3]));
        }
        rmax0 = fmaxf(rmax0, __shfl_xor_sync(0xffffffffu, rmax0, 1));
        rmax0 = fmaxf(rmax0, __shfl_xor_sync(0xffffffffu, rmax0, 2));
        rmax1 = fmaxf(rmax1, __shfl_xor_sync(0xffffffffu, rmax1, 1));
        rmax1 = fmaxf(rmax1, __shfl_xor_sync(0xffffffffu, rmax1, 2));

        float mn0 = fmaxf(m0, rmax0), mn1 = fmaxf(m1, rmax1);
        float cr0 = exp2f(m0 - mn0), cr1 = exp2f(m1 - mn1);
        m0 = mn0; m1 = mn1;
        l0 *= cr0; l1 *= cr1;

        float ps0 = 0.f, ps1 = 0.f;
        uint32_t ph[8][2];
        #pragma unroll
        for (int nt = 0; nt < 8; nt++) {
            float p0 = exp2f(s[nt][0] - m0);
            float p1 = exp2f(s[nt][1] - m0);
            float p2 = exp2f(s[nt][2] - m1);
            float p3 = exp2f(s[nt][3] - m1);
            ps0 += p0 + p1; ps1 += p2 + p3;
            __half2 h01 = __floats2half2_rn(p0, p1);
            __half2 h23 = __floats2half2_rn(p2, p3);
            ph[nt][0] = *(uint32_t*)&h01;
            ph[nt][1] = *(uint32_t*)&h23;
            o[nt][0] *= cr0; o[nt][1] *= cr0;
            o[nt][2] *= cr1; o[nt][3] *= cr1;
        }
        ps0 += __shfl_xor_sync(0xffffffffu, ps0, 1);
        ps0 += __shfl_xor_sync(0xffffffffu, ps0, 2);
        ps1 += __shfl_xor_sync(0xffffffffu, ps1, 1);
        ps1 += __shfl_xor_sync(0xffffffffu, ps1, 2);
        l0 += ps0; l1 += ps1;

        // ---- O += P V ----
        #pragma unroll
        for (int jc = 0; jc < 4; jc++) {
            uint32_t a[4] = { ph[2 * jc][0], ph[2 * jc][1],
                              ph[2 * jc + 1][0], ph[2 * jc + 1][1] };
            #pragma unroll
            for (int dp = 0; dp < 4; dp++) {
                uint32_t b0, b1, b2, b3;
                ldsm4t(vbb + ((jc * 16 + arow) * LQH + dp * 16 + acol) * 2,
                       b0, b1, b2, b3);
                uint32_t bl[2] = { b0, b1 }, bh[2] = { b2, b3 };
                mma_f16(o[2 * dp],     a, bl);
                mma_f16(o[2 * dp + 1], a, bh);
            }
        }
        __syncthreads();
    }

    float inv0 = 1.f / l0, inv1 = 1.f / l1;
    float* og = out + ((size_t)(b * T_) + (size_t)qb * 64 + wid * 16 + g) * H_ + h * HD_;
    #pragma unroll
    for (int nt = 0; nt < 8; nt++) {
        int lc = nt * 8 + 2 * c;
        float2 w0, w1;
        w0.x = o[nt][0] * inv0; w0.y = o[nt][1] * inv0;
        w1.x = o[nt][2] * inv1; w1.y = o[nt][3] * inv1;
        *(float2*)(og + lc)          = w0;
        *(float2*)(og + 8 * H_ + lc) = w1;
    }
}

// ===========================================================================
// Launch
// ===========================================================================
extern "C" void kernel_launch(void* const* d_in, const int* in_sizes, int n_in,
                              void* d_out, int out_size)
{
    const float* x    = (const float*)d_in[0];
    const float* mask = (const float*)d_in[1];
    const float* Wq   = (const float*)d_in[2];
    const float* bq   = (const float*)d_in[3];
    const float* Wk   = (const float*)d_in[4];
    const float* bk   = (const float*)d_in[5];
    const float* Wv   = (const float*)d_in[6];
    const float* bv   = (const float*)d_in[7];
    float* out = (float*)d_out;

    __half *X16p, *W16p;
    cudaGetSymbolAddress((void**)&X16p, g_X16);
    cudaGetSymbolAddress((void**)&W16p, g_W16);

    cudaFuncSetAttribute(qkv_gemm_fp16, cudaFuncAttributeMaxDynamicSharedMemorySize,
                         GEMM_SMEM);

    cvt32to16<<<(M_ * H_ / 8 + 255) / 256, 256>>>(x, X16p, M_ * H_ / 8);
    cvt32to16<<<(H_ * H_ / 8 + 255) / 256, 256>>>(Wq, W16p,               H_ * H_ / 8);
    cvt32to16<<<(H_ * H_ / 8 + 255) / 256, 256>>>(Wk, W16p + H_ * H_,     H_ * H_ / 8);
    cvt32to16<<<(H_ * H_ / 8 + 255) / 256, 256>>>(Wv, W16p + 2 * H_ * H_, H_ * H_ / 8);

    dim3 ggrid(H_ / 128, M_ / 128, 3);   // (8, 64, 3)
    qkv_gemm_fp16<<<ggrid, 256, GEMM_SMEM>>>(bq, bk, bv);

    dim3 agrid(T_ / 64, NH_, B_);        // (32, 16, 4)
    attn_fp16<<<agrid, 128>>>(mask, out);
}